// round 1
// baseline (speedup 1.0000x reference)
#include <cuda_runtime.h>
#include <math.h>
#include <math_constants.h>

#define D_MODEL 768
#define N_HEAD  12
#define N_BR    4
#define DH      64
#define H_TOT   48
#define BATCH   2
#define T_LEN   1024
#define M_ROWS  (BATCH * T_LEN)      // 2048
#define NQ      (D_MODEL * N_BR)     // 3072

// ---------------- scratch (static device allocations; no cudaMalloc allowed) ----
__device__ float g_qraw [M_ROWS * NQ];                       // 25 MB
__device__ float g_kraw [M_ROWS * D_MODEL];                  // 6 MB
__device__ float g_qrope[BATCH * H_TOT * T_LEN * DH];        // 25 MB
__device__ float g_krope[BATCH * H_TOT * T_LEN * DH];        // 25 MB
__device__ float g_ctx  [BATCH * N_BR * T_LEN * D_MODEL];    // 25 MB

// ---------------- generic NT GEMM: C[m][n] = sum_k A[m*K+k] * W[n*K+k] (+bias[n])
// 64x64 tile, 256 threads, 4x4 per thread, TK=16.
__global__ void gemm_nt_kernel(const float* __restrict__ A,
                               const float* __restrict__ W,
                               const float* __restrict__ bias,
                               float* __restrict__ C,
                               int N, int K) {
    __shared__ float As[16][68];
    __shared__ float Bs[16][68];
    const int tid = threadIdx.x;
    const int tx = tid % 16, ty = tid / 16;
    const int m0 = blockIdx.y * 64, n0 = blockIdx.x * 64;

    float acc[4][4];
#pragma unroll
    for (int i = 0; i < 4; i++)
#pragma unroll
        for (int j = 0; j < 4; j++) acc[i][j] = 0.f;

    const int kkl = tid % 16;
    const int rl  = tid / 16;   // 0..15

    for (int k0 = 0; k0 < K; k0 += 16) {
#pragma unroll
        for (int p = 0; p < 4; ++p) {
            int row = rl + p * 16;
            As[kkl][row] = A[(size_t)(m0 + row) * K + k0 + kkl];
            Bs[kkl][row] = W[(size_t)(n0 + row) * K + k0 + kkl];
        }
        __syncthreads();
#pragma unroll
        for (int kk = 0; kk < 16; ++kk) {
            float a[4], b[4];
#pragma unroll
            for (int i = 0; i < 4; i++) a[i] = As[kk][ty * 4 + i];
#pragma unroll
            for (int j = 0; j < 4; j++) b[j] = Bs[kk][tx * 4 + j];
#pragma unroll
            for (int i = 0; i < 4; i++)
#pragma unroll
                for (int j = 0; j < 4; j++) acc[i][j] = fmaf(a[i], b[j], acc[i][j]);
        }
        __syncthreads();
    }
#pragma unroll
    for (int i = 0; i < 4; i++) {
        int m = m0 + ty * 4 + i;
#pragma unroll
        for (int j = 0; j < 4; j++) {
            int n = n0 + tx * 4 + j;
            float v = acc[i][j];
            if (bias) v += bias[n];
            C[(size_t)m * N + n] = v;
        }
    }
}

// ---------------- wedge + rope for Q: qraw[m][h*64+d] -> qrope[b][h][t][d]
__global__ void qwedge_kernel(const float* __restrict__ qraw,
                              const float* __restrict__ wedgeA,
                              const float* __restrict__ wbias,
                              float* __restrict__ qout) {
    __shared__ float skew[64 * 64];
    __shared__ float xrow[NQ];
    __shared__ float wbuf[NQ];
    const int m = blockIdx.x;
    const int b = m >> 10, t = m & 1023;
    const int tid = threadIdx.x;   // 256

    for (int i = tid; i < 4096; i += 256) {
        int e = i >> 6, d = i & 63;
        skew[i] = wedgeA[e * 64 + d] - wedgeA[d * 64 + e];
    }
    for (int i = tid; i < NQ; i += 256) xrow[i] = qraw[(size_t)m * NQ + i];
    __syncthreads();

#pragma unroll
    for (int r = 0; r < 12; ++r) {
        int idx = r * 256 + tid;
        int h = idx >> 6, d = idx & 63;
        const float* x = &xrow[h * 64];
        float acc = x[d] * (1.0f + wbias[h * 64 + d]);
#pragma unroll
        for (int e = 0; e < 64; ++e) acc = fmaf(x[e], skew[e * 64 + d], acc);
        wbuf[idx] = acc;
    }
    __syncthreads();

#pragma unroll
    for (int r = 0; r < 12; ++r) {
        int idx = r * 256 + tid;
        int h = idx >> 6, d = idx & 63;
        const float* w = &wbuf[h * 64];
        int i = d & 31;
        float inv = exp2f(-(float)i * 0.4152410118f);   // 10000^(-i/32)
        float fr = (float)t * inv;
        float cs = cosf(fr), sn = sinf(fr);
        float xe = w[2 * i], xo = w[2 * i + 1];
        float v = (d < 32) ? (xe * cs - xo * sn) : (xe * sn + xo * cs);
        qout[(((size_t)(b * H_TOT + h)) * T_LEN + t) * DH + d] = v;
    }
}

// ---------------- wedge + rope for K (tiled across 48 heads from 12 base heads)
__global__ void kwedge_kernel(const float* __restrict__ kraw,
                              const float* __restrict__ wedgeA,
                              const float* __restrict__ wbias,
                              float* __restrict__ kout) {
    __shared__ float skew[64 * 64];
    __shared__ float xrow[D_MODEL];
    __shared__ float wbuf[NQ];
    const int m = blockIdx.x;
    const int b = m >> 10, t = m & 1023;
    const int tid = threadIdx.x;   // 256

    for (int i = tid; i < 4096; i += 256) {
        int e = i >> 6, d = i & 63;
        skew[i] = wedgeA[e * 64 + d] - wedgeA[d * 64 + e];
    }
    for (int i = tid; i < D_MODEL; i += 256) xrow[i] = kraw[(size_t)m * D_MODEL + i];
    __syncthreads();

#pragma unroll
    for (int r = 0; r < 12; ++r) {
        int idx = r * 256 + tid;
        int h = idx >> 6, d = idx & 63;
        const float* x = &xrow[(h % 12) * 64];
        float acc = x[d] * (1.0f + wbias[h * 64 + d]);
#pragma unroll
        for (int e = 0; e < 64; ++e) acc = fmaf(x[e], skew[e * 64 + d], acc);
        wbuf[idx] = acc;
    }
    __syncthreads();

#pragma unroll
    for (int r = 0; r < 12; ++r) {
        int idx = r * 256 + tid;
        int h = idx >> 6, d = idx & 63;
        const float* w = &wbuf[h * 64];
        int i = d & 31;
        float inv = exp2f(-(float)i * 0.4152410118f);
        float fr = (float)t * inv;
        float cs = cosf(fr), sn = sinf(fr);
        float xe = w[2 * i], xo = w[2 * i + 1];
        float v = (d < 32) ? (xe * cs - xo * sn) : (xe * sn + xo * cs);
        kout[(((size_t)(b * H_TOT + h)) * T_LEN + t) * DH + d] = v;
    }
}

// ---------------- attention: one thread per (b,h,t); blocks of 128 t-rows.
// phase 1: streaming scores over 128-row k tiles in smem; online softmax + top-4
// phase 2: marker gather + MLP(64->256 gelu ->256->64) with V1/V2^T in smem
__global__ void attn_kernel(const float* __restrict__ qrope,
                            const float* __restrict__ krope,
                            const float* __restrict__ sink,
                            const float* __restrict__ vnull,
                            const float* __restrict__ V1w,
                            const float* __restrict__ V1b,
                            const float* __restrict__ V2w,
                            const float* __restrict__ V2b,
                            float* __restrict__ ctx) {
    extern __shared__ float sm[];          // 32768 floats (128 KB)
    __shared__ float sV1b[256];
    __shared__ float sV2b[64];

    const int bh = blockIdx.y;             // 0..95
    const int b = bh / H_TOT, h = bh % H_TOT;
    const int t = blockIdx.x * 128 + threadIdx.x;

    // load q row into registers
    float qv[64];
    {
        const float4* q4 = reinterpret_cast<const float4*>(
            qrope + (((size_t)bh) * T_LEN + t) * DH);
#pragma unroll
        for (int i = 0; i < 16; ++i) {
            float4 v = q4[i];
            qv[4 * i] = v.x; qv[4 * i + 1] = v.y; qv[4 * i + 2] = v.z; qv[4 * i + 3] = v.w;
        }
    }

    float mrun = -CUDART_INF_F, lrun = 0.f;
    float ts0 = -CUDART_INF_F, ts1 = -CUDART_INF_F, ts2 = -CUDART_INF_F, ts3 = -CUDART_INF_F;
    int ti0 = 0, ti1 = 0, ti2 = 0, ti3 = 0;

    float* ks = sm;                         // 128*64 floats tile
    const int sEndBlock = blockIdx.x * 128 + 127;

    for (int s0 = 0; s0 <= sEndBlock; s0 += 128) {
        __syncthreads();
        {
            const float4* kg = reinterpret_cast<const float4*>(
                krope + (((size_t)bh) * T_LEN + s0) * DH);
            float4* d4 = reinterpret_cast<float4*>(ks);
            for (int i = threadIdx.x; i < 128 * 64 / 4; i += 128) d4[i] = kg[i];
        }
        __syncthreads();

        const int sMax = min(t, s0 + 127);
        for (int s = s0; s <= sMax; ++s) {
            const float* kr = ks + (s - s0) * 64;
            float a0 = 0.f, a1 = 0.f, a2 = 0.f, a3 = 0.f;
#pragma unroll
            for (int d = 0; d < 64; d += 4) {
                a0 = fmaf(qv[d],     kr[d],     a0);
                a1 = fmaf(qv[d + 1], kr[d + 1], a1);
                a2 = fmaf(qv[d + 2], kr[d + 2], a2);
                a3 = fmaf(qv[d + 3], kr[d + 3], a3);
            }
            float sc = ((a0 + a1) + (a2 + a3)) * 0.125f;

            // online softmax
            float nm = fmaxf(mrun, sc);
            lrun = lrun * __expf(mrun - nm) + __expf(sc - nm);
            mrun = nm;

            // streaming top-4 (sorted descending; strict > keeps earliest index on tie)
            if (sc > ts3) {
                if (sc > ts2) {
                    ts3 = ts2; ti3 = ti2;
                    if (sc > ts1) {
                        ts2 = ts1; ti2 = ti1;
                        if (sc > ts0) {
                            ts1 = ts0; ti1 = ti0;
                            ts0 = sc; ti0 = s;
                        } else { ts1 = sc; ti1 = s; }
                    } else { ts2 = sc; ti2 = s; }
                } else { ts3 = sc; ti3 = s; }
            }
        }
    }

    // sink + final normalization
    const float sk = sink[h];
    const float mf = fmaxf(mrun, sk);
    const float Z  = lrun * __expf(mrun - mf) + __expf(sk - mf);
    const float invZ = 1.0f / Z;
    const float psink = __expf(sk - mf) * invZ;
    float p0 = __expf(ts0 - mf) * invZ;
    float p1 = __expf(ts1 - mf) * invZ;
    float p2 = __expf(ts2 - mf) * invZ;
    float p3 = __expf(ts3 - mf) * invZ;
    const float winv = 1.0f / (p0 + p1 + p2 + p3 + 1e-9f);
    p0 *= winv; p1 *= winv; p2 *= winv; p3 *= winv;

    // marker = sum_i w_i * k[idx_i]  (reuse qv[] as marker)
    {
        const float* k0p = krope + (((size_t)bh) * T_LEN + ti0) * DH;
        const float* k1p = krope + (((size_t)bh) * T_LEN + ti1) * DH;
        const float* k2p = krope + (((size_t)bh) * T_LEN + ti2) * DH;
        const float* k3p = krope + (((size_t)bh) * T_LEN + ti3) * DH;
#pragma unroll
        for (int d = 0; d < 64; ++d)
            qv[d] = p0 * k0p[d] + p1 * k1p[d] + p2 * k2p[d] + p3 * k3p[d];
    }

    // stage V1 (row-major j,d) and V2^T (j,d) into smem
    __syncthreads();
    float* V1s = sm;            // 16384 floats
    float* V2t = sm + 16384;    // 16384 floats
    for (int i = threadIdx.x; i < 16384; i += 128) V1s[i] = V1w[i];
    for (int i = threadIdx.x; i < 16384; i += 128) {
        int j = i >> 6, d = i & 63;
        V2t[i] = V2w[d * 256 + j];
    }
    for (int i = threadIdx.x; i < 256; i += 128) sV1b[i] = V1b[i];
    if (threadIdx.x < 64) sV2b[threadIdx.x] = V2b[threadIdx.x];
    __syncthreads();

    float out[64];
#pragma unroll
    for (int d = 0; d < 64; ++d) out[d] = sV2b[d];

    for (int j = 0; j < 256; ++j) {
        const float* v1 = V1s + j * 64;
        float a0 = 0.f, a1 = 0.f, a2 = 0.f, a3 = 0.f;
#pragma unroll
        for (int d = 0; d < 64; d += 4) {
            a0 = fmaf(qv[d],     v1[d],     a0);
            a1 = fmaf(qv[d + 1], v1[d + 1], a1);
            a2 = fmaf(qv[d + 2], v1[d + 2], a2);
            a3 = fmaf(qv[d + 3], v1[d + 3], a3);
        }
        float z = ((a0 + a1) + (a2 + a3)) + sV1b[j];
        float g = 0.5f * z * (1.0f + erff(z * 0.70710678118f));   // exact gelu
        const float* v2 = V2t + j * 64;
#pragma unroll
        for (int d = 0; d < 64; ++d) out[d] = fmaf(g, v2[d], out[d]);
    }

    // context write: [b][br][t][hj*64+d] + psink * v_null
    const int br = h / 12, hj = h % 12;
    float* outp = ctx + ((((size_t)b * N_BR + br) * T_LEN + t) * D_MODEL) + hj * 64;
    const float* vn = vnull + h * 64;
#pragma unroll
    for (int d = 0; d < 64; ++d) outp[d] = out[d] + psink * vn[d];
}

// ---------------- output projection: y = (1/4) sum_br ctx_br @ WO_br + mean(WO_b)
// M=2048, N=768, K = 4*768 (br-major)
__global__ void gemm_out_kernel(const float* __restrict__ ctx,
                                const float* __restrict__ WOw,
                                const float* __restrict__ WOb,
                                float* __restrict__ Y) {
    __shared__ float As[16][68];
    __shared__ float Bs[16][68];
    const int tid = threadIdx.x;
    const int tx = tid % 16, ty = tid / 16;
    const int m0 = blockIdx.y * 64, n0 = blockIdx.x * 64;

    float acc[4][4];
#pragma unroll
    for (int i = 0; i < 4; i++)
#pragma unroll
        for (int j = 0; j < 4; j++) acc[i][j] = 0.f;

    const int kkl = tid % 16;
    const int rl  = tid / 16;    // 0..15 (A loads)
    const int jb  = tid & 63;    // B loads
    const int kq  = tid >> 6;    // 0..3

    for (int k0 = 0; k0 < 4 * D_MODEL; k0 += 16) {
        const int br = k0 / D_MODEL;
        const int c0 = k0 % D_MODEL;
#pragma unroll
        for (int p = 0; p < 4; ++p) {
            int row = rl + p * 16;
            int m = m0 + row;
            int bb = m >> 10, tt = m & 1023;
            As[kkl][row] = ctx[(((size_t)(bb * N_BR + br)) * T_LEN + tt) * D_MODEL + c0 + kkl];
        }
#pragma unroll
        for (int p = 0; p < 4; ++p) {
            int kk = kq + p * 4;
            Bs[kk][jb] = WOw[((size_t)br * D_MODEL + c0 + kk) * D_MODEL + n0 + jb];
        }
        __syncthreads();
#pragma unroll
        for (int kk = 0; kk < 16; ++kk) {
            float a[4], b[4];
#pragma unroll
            for (int i = 0; i < 4; i++) a[i] = As[kk][ty * 4 + i];
#pragma unroll
            for (int j = 0; j < 4; j++) b[j] = Bs[kk][tx * 4 + j];
#pragma unroll
            for (int i = 0; i < 4; i++)
#pragma unroll
                for (int j = 0; j < 4; j++) acc[i][j] = fmaf(a[i], b[j], acc[i][j]);
        }
        __syncthreads();
    }
#pragma unroll
    for (int i = 0; i < 4; i++) {
        int m = m0 + ty * 4 + i;
#pragma unroll
        for (int j = 0; j < 4; j++) {
            int n = n0 + tx * 4 + j;
            float mb = 0.25f * (WOb[n] + WOb[D_MODEL + n] + WOb[2 * D_MODEL + n] + WOb[3 * D_MODEL + n]);
            Y[(size_t)m * D_MODEL + n] = 0.25f * acc[i][j] + mb;
        }
    }
}

// ---------------- launcher ----------------
extern "C" void kernel_launch(void* const* d_in, const int* in_sizes, int n_in,
                              void* d_out, int out_size) {
    const float* A      = (const float*)d_in[0];
    const float* X      = (const float*)d_in[1];
    const float* WKw    = (const float*)d_in[2];
    const float* WKb    = (const float*)d_in[3];
    const float* WQw    = (const float*)d_in[4];
    const float* wedgeA = (const float*)d_in[5];
    const float* wbias  = (const float*)d_in[6];
    const float* sink   = (const float*)d_in[7];
    const float* vnull  = (const float*)d_in[8];
    const float* V1w    = (const float*)d_in[9];
    const float* V1b    = (const float*)d_in[10];
    const float* V2w    = (const float*)d_in[11];
    const float* V2b    = (const float*)d_in[12];
    const float* WOw    = (const float*)d_in[13];
    const float* WOb    = (const float*)d_in[14];
    float* Y = (float*)d_out;

    float *qraw, *kraw, *qrope, *krope, *ctx;
    cudaGetSymbolAddress((void**)&qraw,  g_qraw);
    cudaGetSymbolAddress((void**)&kraw,  g_kraw);
    cudaGetSymbolAddress((void**)&qrope, g_qrope);
    cudaGetSymbolAddress((void**)&krope, g_krope);
    cudaGetSymbolAddress((void**)&ctx,   g_ctx);

    cudaFuncSetAttribute(attn_kernel, cudaFuncAttributeMaxDynamicSharedMemorySize, 131072);

    // 1) q = A @ WQ^T
    gemm_nt_kernel<<<dim3(NQ / 64, M_ROWS / 64), 256>>>(A, WQw, nullptr, qraw, NQ, D_MODEL);
    // 2) k = X @ WK^T + b
    gemm_nt_kernel<<<dim3(D_MODEL / 64, M_ROWS / 64), 256>>>(X, WKw, WKb, kraw, D_MODEL, D_MODEL);
    // 3) wedge+rope
    qwedge_kernel<<<M_ROWS, 256>>>(qraw, wedgeA, wbias, qrope);
    kwedge_kernel<<<M_ROWS, 256>>>(kraw, wedgeA, wbias, krope);
    // 4) attention + MLP + sink
    attn_kernel<<<dim3(T_LEN / 128, BATCH * H_TOT), 128, 131072>>>(
        qrope, krope, sink, vnull, V1w, V1b, V2w, V2b, ctx);
    // 5) output projection with branch mean folded in
    gemm_out_kernel<<<dim3(D_MODEL / 64, M_ROWS / 64), 256>>>(ctx, WOw, WOb, Y);
}